// round 1
// baseline (speedup 1.0000x reference)
#include <cuda_runtime.h>
#include <cstdint>

// Problem constants
#define U_   32768
#define FIN  512
#define H1_  512
#define H2_  256
#define GY   64
#define GX   64
#define EPSF 1e-6f

// ---------------------------------------------------------------------------
// Scratch (device globals — no allocation allowed)
// ---------------------------------------------------------------------------
__device__ float g_mean1[U_];
__device__ float g_rstd1[U_];
__device__ float g_h1[(size_t)U_ * H1_];       // 64 MB
__device__ float g_mean2[U_];
__device__ float g_rstd2[U_];
__device__ float g_grid[GY * GX * H2_];        // 4 MB (scatter target)
__device__ float g_gact[GY * GX * H2_];        // 4 MB (post LN3+relu)

// ---------------------------------------------------------------------------
// Row statistics (mean, rstd) for a 512-wide row. 128 threads per row.
// ---------------------------------------------------------------------------
__device__ __forceinline__ void rowstats_body(const float* __restrict__ x,
                                              float* __restrict__ meanArr,
                                              float* __restrict__ rstdArr,
                                              int N) {
    int row = blockIdx.x;
    const float4* xr = (const float4*)(x + (size_t)row * N);
    int n4 = N >> 2;
    float s = 0.f, q = 0.f;
    for (int i = threadIdx.x; i < n4; i += blockDim.x) {
        float4 v = xr[i];
        s += v.x + v.y + v.z + v.w;
        q += v.x * v.x + v.y * v.y + v.z * v.z + v.w * v.w;
    }
#pragma unroll
    for (int o = 16; o > 0; o >>= 1) {
        s += __shfl_down_sync(0xffffffffu, s, o);
        q += __shfl_down_sync(0xffffffffu, q, o);
    }
    __shared__ float ws[4], wq[4];
    int wid = threadIdx.x >> 5;
    if ((threadIdx.x & 31) == 0) { ws[wid] = s; wq[wid] = q; }
    __syncthreads();
    if (threadIdx.x == 0) {
        s = ws[0] + ws[1] + ws[2] + ws[3];
        q = wq[0] + wq[1] + wq[2] + wq[3];
        float n = (float)N;
        float m = s / n;
        float var = q / n - m * m;
        meanArr[row] = m;
        rstdArr[row] = rsqrtf(var + EPSF);
    }
}

__global__ void rowstats1_kernel(const float* __restrict__ z) {
    rowstats_body(z, g_mean1, g_rstd1, FIN);
}
__global__ void rowstats2_kernel() {
    rowstats_body(g_h1, g_mean2, g_rstd2, H1_);
}

// ---------------------------------------------------------------------------
// GEMM1: h1[M=U, N=512] = relu(LN1(z)) @ W1 + b1
// 128x128 block tile, BK=8, 256 threads, 8x8 per thread.
// LN1 + relu fused into the A-tile load.
// ---------------------------------------------------------------------------
#define BM 128
#define BN 128
#define BK 8
#define TM 8
#define TN 8

__global__ void __launch_bounds__(256, 2)
gemm1_kernel(const float* __restrict__ z,
             const float* __restrict__ lnS, const float* __restrict__ lnB,
             const float* __restrict__ W, const float* __restrict__ bias) {
    __shared__ float As[BK][BM];
    __shared__ float Bs[BK][BN];
    __shared__ float sS[FIN], sB[FIN];

    int tid = threadIdx.x;
    for (int i = tid; i < FIN; i += 256) { sS[i] = lnS[i]; sB[i] = lnB[i]; }

    int rowBase = blockIdx.y * BM;
    int colBase = blockIdx.x * BN;

    int aRow = tid >> 1;            // 0..127
    int aCol = (tid & 1) * 4;       // 0 or 4
    int bRow = tid >> 5;            // 0..7
    int bCol = (tid & 31) * 4;      // 0..124

    float m  = g_mean1[rowBase + aRow];
    float rs = g_rstd1[rowBase + aRow];

    int tx = tid & 15, ty = tid >> 4;
    float acc[TM][TN] = {};

    __syncthreads();  // sS/sB ready

    for (int k0 = 0; k0 < FIN; k0 += BK) {
        float4 av = *(const float4*)(z + (size_t)(rowBase + aRow) * FIN + k0 + aCol);
        float4 bv = *(const float4*)(W + (size_t)(k0 + bRow) * H1_ + colBase + bCol);

        int k = k0 + aCol;
        float a0 = fmaxf((av.x - m) * rs * sS[k + 0] + sB[k + 0], 0.f);
        float a1 = fmaxf((av.y - m) * rs * sS[k + 1] + sB[k + 1], 0.f);
        float a2 = fmaxf((av.z - m) * rs * sS[k + 2] + sB[k + 2], 0.f);
        float a3 = fmaxf((av.w - m) * rs * sS[k + 3] + sB[k + 3], 0.f);

        As[aCol + 0][aRow] = a0;
        As[aCol + 1][aRow] = a1;
        As[aCol + 2][aRow] = a2;
        As[aCol + 3][aRow] = a3;
        *(float4*)&Bs[bRow][bCol] = bv;
        __syncthreads();

#pragma unroll
        for (int kk = 0; kk < BK; kk++) {
            float4 A0 = *(float4*)&As[kk][ty * TM];
            float4 A1 = *(float4*)&As[kk][ty * TM + 4];
            float4 B0 = *(float4*)&Bs[kk][tx * TN];
            float4 B1 = *(float4*)&Bs[kk][tx * TN + 4];
            float ra[8] = {A0.x, A0.y, A0.z, A0.w, A1.x, A1.y, A1.z, A1.w};
            float rb[8] = {B0.x, B0.y, B0.z, B0.w, B1.x, B1.y, B1.z, B1.w};
#pragma unroll
            for (int i = 0; i < TM; i++)
#pragma unroll
                for (int j = 0; j < TN; j++)
                    acc[i][j] += ra[i] * rb[j];
        }
        __syncthreads();
    }

    int c0 = colBase + tx * TN;
    float bv[TN];
#pragma unroll
    for (int j = 0; j < TN; j++) bv[j] = bias[c0 + j];
#pragma unroll
    for (int i = 0; i < TM; i++) {
        int r = rowBase + ty * TM + i;
        float* dst = g_h1 + (size_t)r * H1_ + c0;
#pragma unroll
        for (int j = 0; j < TN; j++) dst[j] = acc[i][j] + bv[j];
    }
}

// ---------------------------------------------------------------------------
// GEMM2 + scatter: for each unit row, c = relu(LN2(h1)) @ W2 + b2;
// if non_empty, atomicAdd into grid[uy, ux, :].
// ---------------------------------------------------------------------------
__global__ void __launch_bounds__(256, 2)
gemm2_kernel(const float* __restrict__ lnS, const float* __restrict__ lnB,
             const float* __restrict__ W, const float* __restrict__ bias,
             const int* __restrict__ ux, const int* __restrict__ uy,
             const int* __restrict__ ne) {
    __shared__ float As[BK][BM];
    __shared__ float Bs[BK][BN];
    __shared__ float sS[H1_], sB[H1_];

    int tid = threadIdx.x;
    for (int i = tid; i < H1_; i += 256) { sS[i] = lnS[i]; sB[i] = lnB[i]; }

    int rowBase = blockIdx.y * BM;
    int colBase = blockIdx.x * BN;

    int aRow = tid >> 1;
    int aCol = (tid & 1) * 4;
    int bRow = tid >> 5;
    int bCol = (tid & 31) * 4;

    float m  = g_mean2[rowBase + aRow];
    float rs = g_rstd2[rowBase + aRow];

    int tx = tid & 15, ty = tid >> 4;
    float acc[TM][TN] = {};

    __syncthreads();

    for (int k0 = 0; k0 < H1_; k0 += BK) {
        float4 av = *(const float4*)(g_h1 + (size_t)(rowBase + aRow) * H1_ + k0 + aCol);
        float4 bv = *(const float4*)(W + (size_t)(k0 + bRow) * H2_ + colBase + bCol);

        int k = k0 + aCol;
        float a0 = fmaxf((av.x - m) * rs * sS[k + 0] + sB[k + 0], 0.f);
        float a1 = fmaxf((av.y - m) * rs * sS[k + 1] + sB[k + 1], 0.f);
        float a2 = fmaxf((av.z - m) * rs * sS[k + 2] + sB[k + 2], 0.f);
        float a3 = fmaxf((av.w - m) * rs * sS[k + 3] + sB[k + 3], 0.f);

        As[aCol + 0][aRow] = a0;
        As[aCol + 1][aRow] = a1;
        As[aCol + 2][aRow] = a2;
        As[aCol + 3][aRow] = a3;
        *(float4*)&Bs[bRow][bCol] = bv;
        __syncthreads();

#pragma unroll
        for (int kk = 0; kk < BK; kk++) {
            float4 A0 = *(float4*)&As[kk][ty * TM];
            float4 A1 = *(float4*)&As[kk][ty * TM + 4];
            float4 B0 = *(float4*)&Bs[kk][tx * TN];
            float4 B1 = *(float4*)&Bs[kk][tx * TN + 4];
            float ra[8] = {A0.x, A0.y, A0.z, A0.w, A1.x, A1.y, A1.z, A1.w};
            float rb[8] = {B0.x, B0.y, B0.z, B0.w, B1.x, B1.y, B1.z, B1.w};
#pragma unroll
            for (int i = 0; i < TM; i++)
#pragma unroll
                for (int j = 0; j < TN; j++)
                    acc[i][j] += ra[i] * rb[j];
        }
        __syncthreads();
    }

    int c0 = colBase + tx * TN;
    float bv[TN];
#pragma unroll
    for (int j = 0; j < TN; j++) bv[j] = bias[c0 + j];
#pragma unroll
    for (int i = 0; i < TM; i++) {
        int r = rowBase + ty * TM + i;
        if (ne[r] != 0) {
            int cell = (uy[r] * GX + ux[r]) * H2_;
#pragma unroll
            for (int j = 0; j < TN; j++)
                atomicAdd(&g_grid[cell + c0 + j], acc[i][j] + bv[j]);
        }
    }
}

// ---------------------------------------------------------------------------
// Zero the scatter grid (1M floats)
// ---------------------------------------------------------------------------
__global__ void zero_grid_kernel() {
    int i = blockIdx.x * 256 + threadIdx.x;
    ((float4*)g_grid)[i] = make_float4(0.f, 0.f, 0.f, 0.f);
}

// ---------------------------------------------------------------------------
// LN3 + relu over grid cells (4096 rows of 256)
// ---------------------------------------------------------------------------
__global__ void ln3_kernel(const float* __restrict__ s3, const float* __restrict__ b3) {
    int cell = blockIdx.x;
    int t = threadIdx.x;
    float v = g_grid[(size_t)cell * H2_ + t];
    float s = v, q = v * v;
#pragma unroll
    for (int o = 16; o > 0; o >>= 1) {
        s += __shfl_down_sync(0xffffffffu, s, o);
        q += __shfl_down_sync(0xffffffffu, q, o);
    }
    __shared__ float ws[8], wq[8];
    __shared__ float sm, sr;
    int wid = t >> 5;
    if ((t & 31) == 0) { ws[wid] = s; wq[wid] = q; }
    __syncthreads();
    if (t == 0) {
        s = 0.f; q = 0.f;
#pragma unroll
        for (int i = 0; i < 8; i++) { s += ws[i]; q += wq[i]; }
        float mm = s / (float)H2_;
        float var = q / (float)H2_ - mm * mm;
        sm = mm;
        sr = rsqrtf(var + EPSF);
    }
    __syncthreads();
    g_gact[(size_t)cell * H2_ + t] = fmaxf((v - sm) * sr * s3[t] + b3[t], 0.f);
}

// ---------------------------------------------------------------------------
// 3x3 SAME conv, 256 -> 256 channels over a 64x64 image.
// Block: one y row x one 64-wide co tile. 256 threads, 4x(x) * 4(co) each.
// ---------------------------------------------------------------------------
__global__ void __launch_bounds__(256)
conv_kernel(const float* __restrict__ w, const float* __restrict__ cbias,
            float* __restrict__ out) {
    __shared__ float As[66][32];        // [gx+1][ci] with zero halo rows 0, 65
    __shared__ float Ws[3][32][64];     // [kx][ci][co]

    int tid = threadIdx.x;
    int coBase = blockIdx.x * 64;
    int y = blockIdx.y;
    int tx = tid & 15;       // co quad
    int ty = tid >> 4;       // x quad
    int xBase = ty * 4;
    int coL = tx * 4;

    float acc[4][4] = {};

    for (int ky = 0; ky < 3; ky++) {
        int gy = y + ky - 1;
        if (gy < 0 || gy >= GY) continue;   // uniform across block
        for (int c0 = 0; c0 < H2_; c0 += 32) {
            __syncthreads();   // protect previous tile reads

            // Load weight slab: 3 kx * 32 ci * 64 co = 1536 float4 / 256 thr = 6
#pragma unroll
            for (int it = 0; it < 6; it++) {
                int idx = tid + it * 256;
                int co4 = idx & 15;
                int ci  = (idx >> 4) & 31;
                int kx  = idx >> 9;
                *(float4*)&Ws[kx][ci][co4 * 4] =
                    *(const float4*)(w + ((size_t)((ky * 3 + kx) * H2_ + c0 + ci) * H2_
                                          + coBase + co4 * 4));
            }
            // Zero halo rows (gx = -1 and gx = 64)
            if (tid < 64) {
                int r = (tid < 32) ? 0 : 65;
                As[r][tid & 31] = 0.f;
            }
            // Load activation row: 64 gx * 32 ci = 512 float4 / 256 thr = 2
#pragma unroll
            for (int it = 0; it < 2; it++) {
                int idx = tid + it * 256;
                int gx = idx >> 3;
                int c4 = idx & 7;
                *(float4*)&As[gx + 1][c4 * 4] =
                    *(const float4*)(g_gact + ((size_t)(gy * GX + gx) * H2_ + c0 + c4 * 4));
            }
            __syncthreads();

#pragma unroll 4
            for (int ci = 0; ci < 32; ci++) {
                float av[6];
#pragma unroll
                for (int t = 0; t < 6; t++) av[t] = As[xBase + t][ci];
                float4 w0 = *(float4*)&Ws[0][ci][coL];
                float4 w1 = *(float4*)&Ws[1][ci][coL];
                float4 w2 = *(float4*)&Ws[2][ci][coL];
#pragma unroll
                for (int xi = 0; xi < 4; xi++) {
                    acc[xi][0] += av[xi] * w0.x + av[xi + 1] * w1.x + av[xi + 2] * w2.x;
                    acc[xi][1] += av[xi] * w0.y + av[xi + 1] * w1.y + av[xi + 2] * w2.y;
                    acc[xi][2] += av[xi] * w0.z + av[xi + 1] * w1.z + av[xi + 2] * w2.z;
                    acc[xi][3] += av[xi] * w0.w + av[xi + 1] * w1.w + av[xi + 2] * w2.w;
                }
            }
        }
    }

#pragma unroll
    for (int xi = 0; xi < 4; xi++) {
        int x = xBase + xi;
#pragma unroll
        for (int cj = 0; cj < 4; cj++) {
            int co = coBase + coL + cj;
            out[(size_t)(y * GX + x) * H2_ + co] = acc[xi][cj] + cbias[co];
        }
    }
}

// ---------------------------------------------------------------------------
// Launch
// ---------------------------------------------------------------------------
extern "C" void kernel_launch(void* const* d_in, const int* in_sizes, int n_in,
                              void* d_out, int out_size) {
    const float* z     = (const float*)d_in[0];
    const int*   ux    = (const int*)d_in[1];
    const int*   uy    = (const int*)d_in[2];
    const int*   ne    = (const int*)d_in[3];
    const float* ln1_s = (const float*)d_in[4];
    const float* ln1_b = (const float*)d_in[5];
    const float* W1    = (const float*)d_in[6];
    const float* b1    = (const float*)d_in[7];
    const float* ln2_s = (const float*)d_in[8];
    const float* ln2_b = (const float*)d_in[9];
    const float* W2    = (const float*)d_in[10];
    const float* b2    = (const float*)d_in[11];
    const float* ln3_s = (const float*)d_in[12];
    const float* ln3_b = (const float*)d_in[13];
    const float* cw    = (const float*)d_in[14];
    const float* cb    = (const float*)d_in[15];
    float* out = (float*)d_out;

    (void)in_sizes; (void)n_in; (void)out_size;

    zero_grid_kernel<<<(GY * GX * H2_) / 4 / 256, 256>>>();
    rowstats1_kernel<<<U_, 128>>>(z);
    gemm1_kernel<<<dim3(H1_ / BN, U_ / BM), 256>>>(z, ln1_s, ln1_b, W1, b1);
    rowstats2_kernel<<<U_, 128>>>();
    gemm2_kernel<<<dim3(H2_ / BN, U_ / BM), 256>>>(ln2_s, ln2_b, W2, b2, ux, uy, ne);
    ln3_kernel<<<GY * GX, 256>>>(ln3_s, ln3_b);
    conv_kernel<<<dim3(H2_ / 64, GY), 256>>>(cw, cb, out);
}